// round 4
// baseline (speedup 1.0000x reference)
#include <cuda_runtime.h>
#include <cuda_bf16.h>
#include <cstdint>

#define B_TOK 2048
#define DIM   1024
#define NEXP  8
#define HID   10240
#define ODIM  1024
#define SLOTS 4096
#define KSPLIT 4

__device__ __nv_bfloat16 g_hid_hi[(size_t)SLOTS * HID];
__device__ __nv_bfloat16 g_hid_lo[(size_t)SLOTS * HID];
__device__ float g_partial[(size_t)KSPLIT * SLOTS * ODIM];
__device__ int   g_cnt[NEXP];
__device__ int   g_basee[NEXP];
__device__ int   g_fill[NEXP];
__device__ int   g_rowtok[SLOTS];
__device__ float g_gatec[SLOTS];
__device__ int   g_pos[SLOTS];
__device__ int   g_tok_e[SLOTS];
__device__ float g_tok_g[SLOTS];

__device__ __forceinline__ uint32_t smem_u32(const void* p) {
    uint32_t a;
    asm("{ .reg .u64 t; cvta.to.shared.u64 t, %1; cvt.u32.u64 %0, t; }" : "=r"(a) : "l"(p));
    return a;
}

#define LDSM4(R, ADDR) \
    asm volatile("ldmatrix.sync.aligned.m8n8.x4.shared.b16 {%0,%1,%2,%3}, [%4];" \
                 : "=r"((R)[0]), "=r"((R)[1]), "=r"((R)[2]), "=r"((R)[3]) : "r"(ADDR))

__device__ __forceinline__ void mma16816(float* d, const uint32_t* a, uint32_t b0, uint32_t b1) {
    asm volatile(
        "mma.sync.aligned.m16n8k16.row.col.f32.bf16.bf16.f32 "
        "{%0,%1,%2,%3},{%4,%5,%6,%7},{%8,%9},{%0,%1,%2,%3};"
        : "+f"(d[0]), "+f"(d[1]), "+f"(d[2]), "+f"(d[3])
        : "r"(a[0]), "r"(a[1]), "r"(a[2]), "r"(a[3]), "r"(b0), "r"(b1));
}

__device__ __forceinline__ void split4(float4 v, uint2& hi, uint2& lo) {
    __nv_bfloat162 h01 = __float22bfloat162_rn(make_float2(v.x, v.y));
    __nv_bfloat162 h23 = __float22bfloat162_rn(make_float2(v.z, v.w));
    float2 f01 = __bfloat1622float2(h01);
    float2 f23 = __bfloat1622float2(h23);
    __nv_bfloat162 l01 = __float22bfloat162_rn(make_float2(v.x - f01.x, v.y - f01.y));
    __nv_bfloat162 l23 = __float22bfloat162_rn(make_float2(v.z - f23.x, v.w - f23.y));
    hi.x = *reinterpret_cast<uint32_t*>(&h01);
    hi.y = *reinterpret_cast<uint32_t*>(&h23);
    lo.x = *reinterpret_cast<uint32_t*>(&l01);
    lo.y = *reinterpret_cast<uint32_t*>(&l23);
}

__global__ void init_kernel() {
    if (threadIdx.x < NEXP) { g_cnt[threadIdx.x] = 0; g_fill[threadIdx.x] = 0; }
}

__global__ __launch_bounds__(256) void gate_kernel(
    const float* __restrict__ x1, const float* __restrict__ gw, const float* __restrict__ gb) {
    __shared__ float sgw[NEXP * DIM];
    for (int i = threadIdx.x; i < NEXP * DIM; i += 256) sgw[i] = gw[i];
    __syncthreads();
    int warp = threadIdx.x >> 5, lane = threadIdx.x & 31;
    int t = blockIdx.x * 8 + warp;
    float acc[NEXP];
#pragma unroll
    for (int e = 0; e < NEXP; e++) acc[e] = 0.f;
    const float* xr = x1 + (size_t)t * DIM;
    for (int j = lane; j < DIM; j += 32) {
        float xv = xr[j];
#pragma unroll
        for (int e = 0; e < NEXP; e++) acc[e] = fmaf(xv, sgw[e * DIM + j], acc[e]);
    }
#pragma unroll
    for (int off = 16; off > 0; off >>= 1)
#pragma unroll
        for (int e = 0; e < NEXP; e++) acc[e] += __shfl_down_sync(0xFFFFFFFFu, acc[e], off);
    if (lane == 0) {
        float l[NEXP], p[NEXP], m = -1e30f;
#pragma unroll
        for (int e = 0; e < NEXP; e++) { l[e] = acc[e] + gb[e]; m = fmaxf(m, l[e]); }
        float s = 0.f;
#pragma unroll
        for (int e = 0; e < NEXP; e++) { p[e] = expf(l[e] - m); s += p[e]; }
        float inv = 1.f / s;
        int e0 = 0; float v0 = -1.f;
#pragma unroll
        for (int e = 0; e < NEXP; e++) { p[e] *= inv; if (p[e] > v0) { v0 = p[e]; e0 = e; } }
        int e1 = 0; float v1 = -2.f;
#pragma unroll
        for (int e = 0; e < NEXP; e++) if (e != e0 && p[e] > v1) { v1 = p[e]; e1 = e; }
        g_tok_e[2 * t] = e0;     g_tok_g[2 * t] = v0;
        g_tok_e[2 * t + 1] = e1; g_tok_g[2 * t + 1] = v1;
        atomicAdd(&g_cnt[e0], 1);
        atomicAdd(&g_cnt[e1], 1);
    }
}

__global__ void scan_kernel() {
    if (threadIdx.x == 0) {
        int s = 0;
        for (int e = 0; e < NEXP; e++) { g_basee[e] = s; s += g_cnt[e]; }
    }
}

__global__ void scatter_kernel() {
    int s = blockIdx.x * 256 + threadIdx.x;
    if (s < SLOTS) {
        int e = g_tok_e[s];
        int r = atomicAdd(&g_fill[e], 1);
        int row = g_basee[e] + r;
        g_rowtok[row] = s >> 1;
        g_gatec[row] = g_tok_g[s];
        g_pos[s] = row;
    }
}

// ---------------- grouped GEMM (mma.sync bf16 3-term split, 128x128 tile) ----------------
#define STAGE  65536
#define OFF_AH 0
#define OFF_AL 16384
#define OFF_BH 32768
#define OFF_BL 49152
#define SM_STG 1024
#define SMEM_TOTAL (SM_STG + 2 * STAGE)

template <int MODE>  // 0: fc1 (x2 -> hidden hi/lo), 1: fc2 (hidden -> partial)
__global__ __launch_bounds__(256, 1) void moe_gemm(
    const float* __restrict__ Asrc, const float* __restrict__ Bw, const float* __restrict__ bias) {
    constexpr int K    = MODE ? HID : DIM;
    constexpr int N    = MODE ? ODIM : HID;
    constexpr int NTIL = N / 128;                       // fc1: 80, fc2: 8
    constexpr int NC   = MODE ? (HID / KSPLIT / 64) : (DIM / 64);  // 40 / 16
    const int total = MODE ? NEXP * 16 * NTIL * KSPLIT : NEXP * 16 * NTIL;

    extern __shared__ char smem[];
    int* rts = (int*)smem;
    char* stg = smem + SM_STG;
    uint32_t sbase = smem_u32(smem) + SM_STG;

    int tid = threadIdx.x, l = tid & 31, w = tid >> 5;
    int m0 = (w >> 1) * 32, n0 = (w & 1) * 64;
    int lr = tid >> 1;            // loader row 0..127
    int lc = (tid & 1) * 32;      // loader col base (elements)

    for (int lin = blockIdx.x; lin < total; lin += gridDim.x) {
        int e, mt, nt, ks;
        if (MODE == 0) { nt = lin % NTIL; int q = lin / NTIL; mt = q & 15; e = q >> 4; ks = 0; }
        else { nt = lin % NTIL; int q = lin / NTIL; ks = q & 3; q >>= 2; mt = q & 15; e = q >> 4; }
        int cnt = g_cnt[e];
        int mb = mt * 128;
        if (mb >= cnt) continue;
        int eb = g_basee[e];
        int rv = cnt - mb; if (rv > 128) rv = 128;
        int nb = nt * 128;
        int kofs = MODE ? ks * (K / KSPLIT) : 0;

        __syncthreads();
        if (tid < 128) {
            int r = tid < rv ? tid : rv - 1;
            rts[tid] = MODE ? (eb + mb + r) : g_rowtok[eb + mb + r];
        }
        __syncthreads();

        const float* apf = nullptr;
        const uint4 *aph = nullptr, *apl = nullptr;
        if (MODE == 0) {
            apf = Asrc + (size_t)rts[lr] * DIM + lc;
        } else {
            size_t ab = (size_t)rts[lr] * HID + kofs + lc;
            aph = (const uint4*)(g_hid_hi + ab);
            apl = (const uint4*)(g_hid_lo + ab);
        }
        const float* bp = Bw + ((size_t)e * N + nb + lr) * K + kofs + lc;

        float acc[2][8][4];
#pragma unroll
        for (int mi = 0; mi < 2; mi++)
#pragma unroll
            for (int ni = 0; ni < 8; ni++)
#pragma unroll
                for (int q = 0; q < 4; q++) acc[mi][ni][q] = 0.f;

        float4 pb[8]; float4 pa[8]; uint4 pah[4], pal[4];
#pragma unroll
        for (int j = 0; j < 8; j++) pb[j] = *(const float4*)(bp + j * 4);
        if (MODE == 0) {
#pragma unroll
            for (int j = 0; j < 8; j++) pa[j] = *(const float4*)(apf + j * 4);
        } else {
#pragma unroll
            for (int j = 0; j < 4; j++) { pah[j] = aph[j]; pal[j] = apl[j]; }
        }

        uint32_t rowb = (uint32_t)lr * 128, xv = ((uint32_t)lr & 7) << 4, cb = (uint32_t)lc * 2;
        uint32_t aArow = m0 + (l & 15), aBrow = n0 + (l & 15);
        uint32_t lxor = ((uint32_t)l & 7) << 4;
        uint32_t khalf = ((uint32_t)l >> 4) * 16;

        for (int c = 0; c < NC; c++) {
            char* sb = stg + (c & 1) * STAGE;
            // ---- store staged regs (split fp32 -> bf16 hi/lo) ----
            if (MODE == 0) {
#pragma unroll
                for (int j = 0; j < 8; j++) {
                    uint2 hi, lo; split4(pa[j], hi, lo);
                    uint32_t off = rowb + ((cb + j * 8) ^ xv);
                    *(uint2*)(sb + OFF_AH + off) = hi;
                    *(uint2*)(sb + OFF_AL + off) = lo;
                }
            } else {
#pragma unroll
                for (int j = 0; j < 4; j++) {
                    uint32_t off = rowb + ((cb + j * 16) ^ xv);
                    *(uint4*)(sb + OFF_AH + off) = pah[j];
                    *(uint4*)(sb + OFF_AL + off) = pal[j];
                }
            }
#pragma unroll
            for (int j = 0; j < 8; j++) {
                uint2 hi, lo; split4(pb[j], hi, lo);
                uint32_t off = rowb + ((cb + j * 8) ^ xv);
                *(uint2*)(sb + OFF_BH + off) = hi;
                *(uint2*)(sb + OFF_BL + off) = lo;
            }
            __syncthreads();
            // ---- prefetch next chunk ----
            if (c + 1 < NC) {
                int k1 = (c + 1) * 64;
#pragma unroll
                for (int j = 0; j < 8; j++) pb[j] = *(const float4*)(bp + k1 + j * 4);
                if (MODE == 0) {
#pragma unroll
                    for (int j = 0; j < 8; j++) pa[j] = *(const float4*)(apf + k1 + j * 4);
                } else {
#pragma unroll
                    for (int j = 0; j < 4; j++) { pah[j] = aph[(c + 1) * 8 + j]; pal[j] = apl[(c + 1) * 8 + j]; }
                }
            }
            // ---- compute 4 k16 steps ----
            uint32_t s32 = sbase + (c & 1) * STAGE;
#pragma unroll
            for (int kt = 0; kt < 4; kt++) {
                uint32_t kb = (((uint32_t)kt * 32) + khalf) ^ lxor;
                uint32_t ah[2][4], al_[2][4], bh[4][4], bl_[4][4];
#pragma unroll
                for (int mi = 0; mi < 2; mi++) {
                    uint32_t ad = s32 + OFF_AH + (aArow + mi * 16) * 128 + kb;
                    LDSM4(ah[mi], ad);
                    LDSM4(al_[mi], ad + (OFF_AL - OFF_AH));
                }
#pragma unroll
                for (int ng = 0; ng < 4; ng++) {
                    uint32_t bd = s32 + OFF_BH + (aBrow + ng * 16) * 128 + kb;
                    LDSM4(bh[ng], bd);
                    LDSM4(bl_[ng], bd + (OFF_BL - OFF_BH));
                }
#pragma unroll
                for (int mi = 0; mi < 2; mi++)
#pragma unroll
                    for (int ng = 0; ng < 4; ng++)
#pragma unroll
                        for (int p = 0; p < 2; p++) {
                            int ni = ng * 2 + p;
                            mma16816(acc[mi][ni], ah[mi], bh[ng][p], bh[ng][p + 2]);
                            mma16816(acc[mi][ni], al_[mi], bh[ng][p], bh[ng][p + 2]);
                            mma16816(acc[mi][ni], ah[mi], bl_[ng][p], bl_[ng][p + 2]);
                        }
            }
        }
        // ---- epilogue ----
        int rbase = eb + mb;
#pragma unroll
        for (int mi = 0; mi < 2; mi++)
#pragma unroll
            for (int h = 0; h < 2; h++) {
                int r = m0 + mi * 16 + (l >> 2) + h * 8;
                if (r >= rv) continue;
                if (MODE == 0) {
                    size_t ro = (size_t)(rbase + r) * HID + nb;
#pragma unroll
                    for (int ni = 0; ni < 8; ni++) {
                        int col = n0 + ni * 8 + (l & 3) * 2;
                        float2 bv = *(const float2*)(bias + (size_t)e * N + nb + col);
                        float2 o;
                        o.x = fmaxf(acc[mi][ni][h * 2 + 0] + bv.x, 0.f);
                        o.y = fmaxf(acc[mi][ni][h * 2 + 1] + bv.y, 0.f);
                        __nv_bfloat162 h2 = __float22bfloat162_rn(o);
                        float2 hf = __bfloat1622float2(h2);
                        __nv_bfloat162 l2 = __float22bfloat162_rn(make_float2(o.x - hf.x, o.y - hf.y));
                        *(__nv_bfloat162*)(g_hid_hi + ro + col) = h2;
                        *(__nv_bfloat162*)(g_hid_lo + ro + col) = l2;
                    }
                } else {
                    float gs = g_gatec[rbase + r];
                    float* orow = g_partial + ((size_t)ks * SLOTS + rbase + r) * ODIM + nb;
#pragma unroll
                    for (int ni = 0; ni < 8; ni++) {
                        int col = n0 + ni * 8 + (l & 3) * 2;
                        float2 o;
                        o.x = acc[mi][ni][h * 2 + 0];
                        o.y = acc[mi][ni][h * 2 + 1];
                        if (ks == 0) {
                            float2 bv = *(const float2*)(bias + (size_t)e * N + nb + col);
                            o.x += bv.x; o.y += bv.y;
                        }
                        o.x *= gs; o.y *= gs;
                        *(float2*)(orow + col) = o;
                    }
                }
            }
    }
}

__global__ __launch_bounds__(256) void combine_kernel(float* __restrict__ out) {
    int i = blockIdx.x * 256 + threadIdx.x;
    int t = i >> 8, c = i & 255;
    int p0 = g_pos[2 * t], p1 = g_pos[2 * t + 1];
    const float4* P = (const float4*)g_partial;
    float4 s = make_float4(0.f, 0.f, 0.f, 0.f);
#pragma unroll
    for (int kk = 0; kk < KSPLIT; kk++) {
        float4 a = P[((size_t)kk * SLOTS + p0) * 256 + c];
        float4 b = P[((size_t)kk * SLOTS + p1) * 256 + c];
        s.x += a.x + b.x; s.y += a.y + b.y; s.z += a.z + b.z; s.w += a.w + b.w;
    }
    ((float4*)out)[i] = s;
}

extern "C" void kernel_launch(void* const* d_in, const int* in_sizes, int n_in,
                              void* d_out, int out_size) {
    const float* x1     = (const float*)d_in[0];
    const float* x2     = (const float*)d_in[1];
    const float* gate_w = (const float*)d_in[2];
    const float* gate_b = (const float*)d_in[3];
    const float* fc1_w  = (const float*)d_in[4];
    const float* fc1_b  = (const float*)d_in[5];
    const float* fc2_w  = (const float*)d_in[6];
    const float* fc2_b  = (const float*)d_in[7];

    cudaFuncSetAttribute(moe_gemm<0>, cudaFuncAttributeMaxDynamicSharedMemorySize, SMEM_TOTAL);
    cudaFuncSetAttribute(moe_gemm<1>, cudaFuncAttributeMaxDynamicSharedMemorySize, SMEM_TOTAL);

    init_kernel<<<1, 32>>>();
    gate_kernel<<<B_TOK / 8, 256>>>(x1, gate_w, gate_b);
    scan_kernel<<<1, 32>>>();
    scatter_kernel<<<SLOTS / 256, 256>>>();
    moe_gemm<0><<<148, 256, SMEM_TOTAL>>>(x2, fc1_w, fc1_b);
    moe_gemm<1><<<148, 256, SMEM_TOTAL>>>(x2, fc2_w, fc2_b);
    combine_kernel<<<(B_TOK * ODIM / 4) / 256, 256>>>((float*)d_out);
}